// round 15
// baseline (speedup 1.0000x reference)
#include <cuda_runtime.h>
#include <cuda_bf16.h>

// LSTM_24936580121326 R15: R9 structure (constant gate-pair f32x2) with
// THREE batch elements per thread — each LDC weight load feeds 3 elements,
// pushing the binder from the half-rate constant port to the fp32 FMA
// roofline (~25 cyc/elem-step).

#define T_STEPS 49
#define NE 3                    // elements per thread

typedef unsigned long long u64;

struct WPack {
    ulonglong2 w1if[8][4];   // layer1 W_hh rows (i,f) scaled 0.5
    ulonglong2 w1go[8][4];   // layer1 W_hh rows (g unscaled, o 0.5)
    ulonglong2 w2uif[8][4];  // layer2 W_ih
    ulonglong2 w2ugo[8][4];
    ulonglong2 w2vif[8][4];  // layer2 W_hh
    ulonglong2 w2vgo[8][4];
    u64 wx_if[8], wx_go[8];  // layer1 W_ih (input dim 1)
    u64 b1if[8], b1go[8];
    u64 b2if[8], b2go[8];
    float wlin[8];
    float blin;
};

__device__   WPack g_wtmp;
__constant__ WPack c_w;

__device__ __forceinline__ u64 pack2(float lo, float hi) {
    u64 r; asm("mov.b64 %0, {%1, %2};" : "=l"(r) : "f"(lo), "f"(hi)); return r;
}
__device__ __forceinline__ void unpack2(u64 v, float& lo, float& hi) {
    asm("mov.b64 {%0, %1}, %2;" : "=f"(lo), "=f"(hi) : "l"(v));
}
__device__ __forceinline__ u64 fma2(u64 a, u64 b, u64 c) {
    u64 d; asm("fma.rn.f32x2 %0, %1, %2, %3;" : "=l"(d) : "l"(a), "l"(b), "l"(c)); return d;
}
__device__ __forceinline__ float tanhf_hw(float x) {
    float y; asm("tanh.approx.f32 %0, %1;" : "=f"(y) : "f"(x)); return y;
}
__device__ __forceinline__ float sig_folded(float zh) {   // pre-halved input
    return fmaf(0.5f, tanhf_hw(zh), 0.5f);
}

// ---------------- preproc (identical to R9) ----------------
__global__ void prep_weights_kernel(
    const float* __restrict__ W_ih0, const float* __restrict__ W_hh0,
    const float* __restrict__ b_ih0, const float* __restrict__ b_hh0,
    const float* __restrict__ W_ih1, const float* __restrict__ W_hh1,
    const float* __restrict__ b_ih1, const float* __restrict__ b_hh1,
    const float* __restrict__ W_lin, const float* __restrict__ b_lin)
{
    int tid = threadIdx.x;
    if (tid < 128) {
        int u = tid >> 4, q = (tid >> 2) & 3, s = tid & 3;
        int col = 2 * q + (s >> 1);
        int sel = s & 1;
        int idx = (u * 4 + q) * 4 + s;
        int gIF = u + 8 * sel;           // i or f
        int gGO = u + 16 + 8 * sel;      // g or o
        float scGO = sel ? 0.5f : 1.0f;
        ((float*)g_wtmp.w1if)[idx]  = 0.5f * W_hh0[gIF * 8 + col];
        ((float*)g_wtmp.w1go)[idx]  = scGO * W_hh0[gGO * 8 + col];
        ((float*)g_wtmp.w2uif)[idx] = 0.5f * W_ih1[gIF * 8 + col];
        ((float*)g_wtmp.w2ugo)[idx] = scGO * W_ih1[gGO * 8 + col];
        ((float*)g_wtmp.w2vif)[idx] = 0.5f * W_hh1[gIF * 8 + col];
        ((float*)g_wtmp.w2vgo)[idx] = scGO * W_hh1[gGO * 8 + col];
    }
    if (tid < 8) {
        int u = tid;
        float* p;
        p = (float*)g_wtmp.wx_if; p[2*u] = 0.5f * W_ih0[u];      p[2*u+1] = 0.5f * W_ih0[u+8];
        p = (float*)g_wtmp.wx_go; p[2*u] =        W_ih0[u+16];   p[2*u+1] = 0.5f * W_ih0[u+24];
        p = (float*)g_wtmp.b1if;  p[2*u] = 0.5f*(b_ih0[u]+b_hh0[u]);
                                  p[2*u+1] = 0.5f*(b_ih0[u+8]+b_hh0[u+8]);
        p = (float*)g_wtmp.b1go;  p[2*u] =       (b_ih0[u+16]+b_hh0[u+16]);
                                  p[2*u+1] = 0.5f*(b_ih0[u+24]+b_hh0[u+24]);
        p = (float*)g_wtmp.b2if;  p[2*u] = 0.5f*(b_ih1[u]+b_hh1[u]);
                                  p[2*u+1] = 0.5f*(b_ih1[u+8]+b_hh1[u+8]);
        p = (float*)g_wtmp.b2go;  p[2*u] =       (b_ih1[u+16]+b_hh1[u+16]);
                                  p[2*u+1] = 0.5f*(b_ih1[u+24]+b_hh1[u+24]);
        g_wtmp.wlin[u] = W_lin[u];
    }
    if (tid == 0) g_wtmp.blin = b_lin[0];
}

// ---------------- fused LSTM: 3 elements per thread ----------------
__global__ void __launch_bounds__(256) lstm_fused_kernel(
    const float* __restrict__ X, float* __restrict__ out, int Bn)
{
    int tid  = threadIdx.x;
    int base = blockIdx.x * (256 * NE) + tid;

    int  be[NE];
    bool ve[NE];
    const float* xp[NE];
#pragma unroll
    for (int e = 0; e < NE; ++e) {
        be[e] = base + e * 256;
        ve[e] = be[e] < Bn;
        xp[e] = X + (long long)(ve[e] ? be[e] : 0) * T_STEPS;
    }

    u64 hp1[NE][8], hp2[NE][8];     // {h,h} splats
    float c1[NE][8], c2[NE][8];
    u64 zero = pack2(0.f, 0.f);
#pragma unroll
    for (int e = 0; e < NE; ++e)
#pragma unroll
        for (int u = 0; u < 8; ++u) {
            hp1[e][u] = hp2[e][u] = zero;
            c1[e][u] = c2[e][u] = 0.f;
        }

    for (int t = 0; t < T_STEPS; ++t) {
        u64 xx[NE];
#pragma unroll
        for (int e = 0; e < NE; ++e) {
            float x = __ldg(xp[e] + t);
            xx[e] = pack2(x, x);
        }

        // ---------- layer 1 ----------
        u64 hn1[NE][8];
#pragma unroll
        for (int u = 0; u < 8; ++u) {
            u64 wxi = c_w.wx_if[u], wxg = c_w.wx_go[u];
            u64 bi  = c_w.b1if[u],  bg  = c_w.b1go[u];
            u64 aif[NE], ago[NE];
#pragma unroll
            for (int e = 0; e < NE; ++e) {
                aif[e] = fma2(wxi, xx[e], bi);
                ago[e] = fma2(wxg, xx[e], bg);
            }
#pragma unroll
            for (int q = 0; q < 4; ++q) {
                ulonglong2 wi = c_w.w1if[u][q];
                ulonglong2 wg = c_w.w1go[u][q];
#pragma unroll
                for (int e = 0; e < NE; ++e) {
                    u64 hL = hp1[e][2*q], hH = hp1[e][2*q+1];
                    aif[e] = fma2(wi.x, hL, aif[e]);
                    aif[e] = fma2(wi.y, hH, aif[e]);
                    ago[e] = fma2(wg.x, hL, ago[e]);
                    ago[e] = fma2(wg.y, hH, ago[e]);
                }
            }
#pragma unroll
            for (int e = 0; e < NE; ++e) {
                float zi, zf, zg, zo;
                unpack2(aif[e], zi, zf);
                unpack2(ago[e], zg, zo);
                float ig = sig_folded(zi), fg = sig_folded(zf);
                float gg = tanhf_hw(zg),  og = sig_folded(zo);
                c1[e][u] = fmaf(fg, c1[e][u], ig * gg);
                float h = og * tanhf_hw(c1[e][u]);
                hn1[e][u] = pack2(h, h);
            }
        }

        // ---------- layer 2 ----------
        u64 hn2[NE][8];
#pragma unroll
        for (int u = 0; u < 8; ++u) {
            u64 bi = c_w.b2if[u], bg = c_w.b2go[u];
            u64 aif[NE], ago[NE];
#pragma unroll
            for (int e = 0; e < NE; ++e) { aif[e] = bi; ago[e] = bg; }
#pragma unroll
            for (int q = 0; q < 4; ++q) {
                ulonglong2 ui = c_w.w2uif[u][q];
                ulonglong2 ug = c_w.w2ugo[u][q];
#pragma unroll
                for (int e = 0; e < NE; ++e) {
                    u64 hL = hn1[e][2*q], hH = hn1[e][2*q+1];
                    aif[e] = fma2(ui.x, hL, aif[e]);
                    aif[e] = fma2(ui.y, hH, aif[e]);
                    ago[e] = fma2(ug.x, hL, ago[e]);
                    ago[e] = fma2(ug.y, hH, ago[e]);
                }
            }
#pragma unroll
            for (int q = 0; q < 4; ++q) {
                ulonglong2 vi = c_w.w2vif[u][q];
                ulonglong2 vg = c_w.w2vgo[u][q];
#pragma unroll
                for (int e = 0; e < NE; ++e) {
                    u64 hL = hp2[e][2*q], hH = hp2[e][2*q+1];
                    aif[e] = fma2(vi.x, hL, aif[e]);
                    aif[e] = fma2(vi.y, hH, aif[e]);
                    ago[e] = fma2(vg.x, hL, ago[e]);
                    ago[e] = fma2(vg.y, hH, ago[e]);
                }
            }
#pragma unroll
            for (int e = 0; e < NE; ++e) {
                float zi, zf, zg, zo;
                unpack2(aif[e], zi, zf);
                unpack2(ago[e], zg, zo);
                float ig = sig_folded(zi), fg = sig_folded(zf);
                float gg = tanhf_hw(zg),  og = sig_folded(zo);
                c2[e][u] = fmaf(fg, c2[e][u], ig * gg);
                float h = og * tanhf_hw(c2[e][u]);
                hn2[e][u] = pack2(h, h);
            }
        }

#pragma unroll
        for (int e = 0; e < NE; ++e)
#pragma unroll
            for (int u = 0; u < 8; ++u) {
                hp1[e][u] = hn1[e][u];
                hp2[e][u] = hn2[e][u];
            }
    }

    // ---------- relu -> linear -> relu ----------
#pragma unroll
    for (int e = 0; e < NE; ++e) {
        float acc = c_w.blin;
#pragma unroll
        for (int u = 0; u < 8; ++u) {
            float h, d;
            unpack2(hp2[e][u], h, d);
            acc = fmaf(c_w.wlin[u], fmaxf(h, 0.0f), acc);
        }
        if (ve[e]) out[be[e]] = fmaxf(acc, 0.0f);
    }
}

extern "C" void kernel_launch(void* const* d_in, const int* in_sizes, int n_in,
                              void* d_out, int out_size) {
    const float* X     = (const float*)d_in[0];
    const float* W_ih0 = (const float*)d_in[1];
    const float* W_hh0 = (const float*)d_in[2];
    const float* b_ih0 = (const float*)d_in[3];
    const float* b_hh0 = (const float*)d_in[4];
    const float* W_ih1 = (const float*)d_in[5];
    const float* W_hh1 = (const float*)d_in[6];
    const float* b_ih1 = (const float*)d_in[7];
    const float* b_hh1 = (const float*)d_in[8];
    const float* W_lin = (const float*)d_in[9];
    const float* b_lin = (const float*)d_in[10];

    int Bn = out_size;

    prep_weights_kernel<<<1, 256>>>(
        W_ih0, W_hh0, b_ih0, b_hh0,
        W_ih1, W_hh1, b_ih1, b_hh1, W_lin, b_lin);

    void* src = nullptr;
    cudaGetSymbolAddress(&src, g_wtmp);
    cudaMemcpyToSymbolAsync(c_w, src, sizeof(WPack), 0,
                            cudaMemcpyDeviceToDevice, 0);

    int epb = 256 * NE;
    int blocks = (Bn + epb - 1) / epb;
    lstm_fused_kernel<<<blocks, 256>>>(X, (float*)d_out, Bn);
}